// round 5
// baseline (speedup 1.0000x reference)
#include <cuda_runtime.h>
#include <cuda_fp16.h>
#include <cstdint>

#define N_ROWS 4096
#define VOCAB  50000
#define VPAD   50048            // 391 * 128
#define DIM    64

#define BM 128
#define BN 128
#define TPB   391               // column tiles per row-block
#define MB    32                // row blocks
#define TOTAL (TPB * MB)        // 12512
#define GRID_P 296              // 2 CTAs/SM x 148 SMs, all resident
#define LAGT  (2 * TPB)         // B-phase lags A-phase by 2 row-blocks
#define EBUF  4                 // E ring depth (blocks)

#define AS_STRIDE 72            // halves; conflict-free fragment LDS

// scratch (no allocs allowed -> device globals)
__device__ float  g_sums[N_ROWS];
__device__ float  g_loss;
__device__ int    g_loss_cnt;
__device__ int    g_done[MB];
__device__ int    g_bdone[MB];
__device__ __half g_A16[N_ROWS * DIM];
__device__ __half g_B16[VOCAB * DIM];
__device__ __half g_E[(size_t)EBUF * BM * VPAD];   // 51.25 MB ring, ~L2 resident

__device__ __forceinline__ int ld_acq(const int* p) {
    int v;
    asm volatile("ld.acquire.gpu.b32 %0, [%1];" : "=r"(v) : "l"(p) : "memory");
    return v;
}

// init + fp32 -> fp16 convert (fp16 keeps tf32's 10 mantissa bits)
__global__ void convert_kernel(const float* __restrict__ A, const float* __restrict__ B) {
    int i = blockIdx.x * blockDim.x + threadIdx.x;               // float4 index
    if (i < N_ROWS) g_sums[i] = 0.f;
    if (i < MB) { g_done[i] = 0; g_bdone[i] = 0; }
    if (i == 0) { g_loss = 0.f; g_loss_cnt = 0; }

    const int nA4 = N_ROWS * DIM / 4;
    const int nB4 = VOCAB * DIM / 4;
    if (i < nA4) {
        float4 v = ((const float4*)A)[i];
        __half2* d = (__half2*)g_A16;
        d[i * 2 + 0] = __floats2half2_rn(v.x, v.y);
        d[i * 2 + 1] = __floats2half2_rn(v.z, v.w);
    }
    int j = i - nA4;
    if (j >= 0 && j < nB4) {
        float4 v = ((const float4*)B)[j];
        __half2* d = (__half2*)g_B16;
        d[j * 2 + 0] = __floats2half2_rn(v.x, v.y);
        d[j * 2 + 1] = __floats2half2_rn(v.z, v.w);
    }
}

// Persistent single-GEMM kernel:
//   A-phase(tile g):  GEMM -> exp -> fp16 E into ring + row-sum atomics -> done[m]++
//   B-phase(g-LAGT):  spin done[m'], read E, scale by 1/sum, stream probs out
__global__ void __launch_bounds__(256, 2)
persistent_kernel(float* __restrict__ out)          // [N_ROWS, VOCAB]
{
    __shared__ __half As[BM * AS_STRIDE];
    __shared__ __half Bs[BN * AS_STRIDE];
    __shared__ float  rowsum[BM];

    const int tid  = threadIdx.x;
    const int lane = tid & 31;
    const int wid  = tid >> 5;
    const int wm = wid >> 2, wn = wid & 3;
    const int mBase = wm * 64, nBase = wn * 32;
    const int lr = lane >> 2, lc = lane & 3;

    for (int g = blockIdx.x; g < TOTAL + LAGT; g += GRID_P) {
        const bool hasA = (g < TOTAL);
        int m = 0, v0 = 0, m0 = 0;

        // ---- A-phase part 1: issue smem tile loads (completes under B-phase) ----
        if (hasA) {
            m = g / TPB; m0 = m * BM; v0 = (g % TPB) * BN;
            const uint4* Ag = (const uint4*)(g_A16 + (size_t)m0 * DIM);
            #pragma unroll
            for (int t = 0; t < 4; t++) {
                int i = tid + t * 256;
                int row = i >> 3, c8 = i & 7;
                *(uint4*)&As[row * AS_STRIDE + c8 * 8] = Ag[row * 8 + c8];
            }
            #pragma unroll
            for (int t = 0; t < 4; t++) {
                int i = tid + t * 256;
                int row = i >> 3, c8 = i & 7;
                int v = v0 + row;
                uint4 val = make_uint4(0u, 0u, 0u, 0u);
                if (v < VOCAB) val = ((const uint4*)(g_B16 + (size_t)v * DIM))[c8];
                *(uint4*)&Bs[row * AS_STRIDE + c8 * 8] = val;
            }
        }

        // ---- B-phase: scale + store probs for tile g - LAGT ----
        const int gb = g - LAGT;
        if (gb >= 0) {
            const int mb = gb / TPB;
            const int vb = (gb % TPB) * BN;
            const int mb0 = mb * BM;
            while (ld_acq(&g_done[mb]) < TPB) __nanosleep(64);

            const int r = tid >> 1, h = tid & 1;       // row 0..127, col half
            const float inv = 1.0f / __ldcg(&g_sums[mb0 + r]);
            const __half* ep = g_E + (size_t)(mb & (EBUF - 1)) * BM * VPAD
                                   + (size_t)r * VPAD + vb + h * 64;
            float* op = out + (size_t)(mb0 + r) * VOCAB + vb + h * 64;
            #pragma unroll
            for (int k = 0; k < 8; k++) {
                int col = vb + h * 64 + k * 8;
                if (col < VOCAB) {
                    uint4 e = __ldcg((const uint4*)(ep + k * 8));
                    float2 f0 = __half22float2(*(__half2*)&e.x);
                    float2 f1 = __half22float2(*(__half2*)&e.y);
                    float2 f2 = __half22float2(*(__half2*)&e.z);
                    float2 f3 = __half22float2(*(__half2*)&e.w);
                    float4 o0 = make_float4(f0.x * inv, f0.y * inv, f1.x * inv, f1.y * inv);
                    float4 o1 = make_float4(f2.x * inv, f2.y * inv, f3.x * inv, f3.y * inv);
                    __stcs((float4*)(op + k * 8), o0);
                    __stcs((float4*)(op + k * 8 + 4), o1);
                }
            }
        }

        // ---- A-phase part 2: MMA + exp + E store + sums ----
        if (hasA) {
            __syncthreads();            // tiles ready

            float c[4][4][4];
            #pragma unroll
            for (int a = 0; a < 4; a++)
                #pragma unroll
                for (int b = 0; b < 4; b++)
                    #pragma unroll
                    for (int d = 0; d < 4; d++) c[a][b][d] = 0.f;

            #pragma unroll
            for (int kk = 0; kk < 4; kk++) {
                unsigned af[4][4], bf[4][2];
                #pragma unroll
                for (int mf = 0; mf < 4; mf++) {
                    const __half* base = &As[(mBase + mf * 16 + lr) * AS_STRIDE + kk * 16 + 2 * lc];
                    af[mf][0] = *(const unsigned*)(base);
                    af[mf][1] = *(const unsigned*)(base + 8 * AS_STRIDE);
                    af[mf][2] = *(const unsigned*)(base + 8);
                    af[mf][3] = *(const unsigned*)(base + 8 * AS_STRIDE + 8);
                }
                #pragma unroll
                for (int nf = 0; nf < 4; nf++) {
                    const __half* base = &Bs[(nBase + nf * 8 + lr) * AS_STRIDE + kk * 16 + 2 * lc];
                    bf[nf][0] = *(const unsigned*)(base);
                    bf[nf][1] = *(const unsigned*)(base + 8);
                }
                #pragma unroll
                for (int mf = 0; mf < 4; mf++)
                    #pragma unroll
                    for (int nf = 0; nf < 4; nf++) {
                        asm volatile(
                            "mma.sync.aligned.m16n8k16.row.col.f32.f16.f16.f32 "
                            "{%0,%1,%2,%3}, {%4,%5,%6,%7}, {%8,%9}, {%0,%1,%2,%3};"
                            : "+f"(c[mf][nf][0]), "+f"(c[mf][nf][1]),
                              "+f"(c[mf][nf][2]), "+f"(c[mf][nf][3])
                            : "r"(af[mf][0]), "r"(af[mf][1]), "r"(af[mf][2]), "r"(af[mf][3]),
                              "r"(bf[nf][0]), "r"(bf[nf][1]));
                    }
            }

            // E-ring overwrite guard: block m reuses slot of block m-EBUF
            if (m >= EBUF) {
                while (ld_acq(&g_bdone[m - EBUF]) < TPB) __nanosleep(64);
            }

            __syncthreads();
            if (tid < BM) rowsum[tid] = 0.f;
            __syncthreads();

            __half* eb = g_E + (size_t)(m & (EBUF - 1)) * BM * VPAD;
            #pragma unroll
            for (int mf = 0; mf < 4; mf++) {
                #pragma unroll
                for (int h = 0; h < 2; h++) {
                    const int rl = mBase + mf * 16 + h * 8 + lr;
                    __half* erow = eb + (size_t)rl * VPAD + v0 + nBase + lc * 2;
                    float s = 0.f;
                    #pragma unroll
                    for (int nf = 0; nf < 4; nf++) {
                        float e0 = __expf(c[mf][nf][h * 2 + 0]);
                        float e1 = __expf(c[mf][nf][h * 2 + 1]);
                        int col = v0 + nBase + nf * 8 + lc * 2;
                        s += (col     < VOCAB) ? e0 : 0.f;
                        s += (col + 1 < VOCAB) ? e1 : 0.f;
                        *(__half2*)(erow + nf * 8) = __floats2half2_rn(e0, e1);
                    }
                    s += __shfl_xor_sync(0xffffffffu, s, 1);
                    s += __shfl_xor_sync(0xffffffffu, s, 2);
                    if (lc == 0) atomicAdd(&rowsum[rl], s);
                }
            }
            __syncthreads();
            if (tid < BM) atomicAdd(&g_sums[m0 + tid], rowsum[tid]);
            __threadfence();
            __syncthreads();
            if (tid == 0) atomicAdd(&g_done[m], 1);
        }

        // ---- B-phase completion signal (probs stored above) ----
        if (gb >= 0) {
            __threadfence();
            __syncthreads();
            if (tid == 0) atomicAdd(&g_bdone[gb / TPB], 1);
        }
    }
}

// loss = mean_n( log(sum_n) - logit_label_n ); clip never binds (min prob ~2e-6 >> 1e-7)
// last block also writes the final scalar (finalize fused via completion counter).
__global__ void loss_kernel(const int* __restrict__ label_words,
                            const float* __restrict__ inp,
                            const float* __restrict__ emb,
                            float* __restrict__ out, long long idx) {
    int n = blockIdx.x * blockDim.x + threadIdx.x;

    // dtype sniff: int64 labels (< 2^31) have all odd 32-bit words == 0
    bool is64 = true;
    #pragma unroll
    for (int i = 0; i < 64; i++) is64 &= (label_words[2 * i + 1] == 0);

    float v = 0.f;
    if (n < N_ROWS) {
        int lab = is64 ? label_words[2 * n] : label_words[n];
        const float4* a = (const float4*)(inp + (size_t)n * DIM);
        const float4* b = (const float4*)(emb + (size_t)lab * DIM);
        float dot = 0.f;
        #pragma unroll
        for (int i = 0; i < DIM / 4; i++) {
            float4 x = a[i], y = b[i];
            dot += x.x * y.x + x.y * y.y + x.z * y.z + x.w * y.w;
        }
        v = logf(g_sums[n]) - dot;
    }
    __shared__ float red[256];
    red[threadIdx.x] = v;
    __syncthreads();
    for (int s = 128; s > 0; s >>= 1) {
        if (threadIdx.x < s) red[threadIdx.x] += red[threadIdx.x + s];
        __syncthreads();
    }
    if (threadIdx.x == 0) {
        atomicAdd(&g_loss, red[0]);
        __threadfence();
        int c = atomicAdd(&g_loss_cnt, 1);
        if (c == (int)gridDim.x - 1) {
            float total = atomicAdd(&g_loss, 0.f);   // ordered read of final sum
            out[idx] = total * (1.0f / (float)N_ROWS);
        }
    }
}

extern "C" void kernel_launch(void* const* d_in, const int* in_sizes, int n_in,
                              void* d_out, int out_size) {
    const int*   label = (const int*)d_in[0];      // int32 or int64 (sniffed in-kernel)
    const float* inp   = (const float*)d_in[1];    // [4096, 64]
    const float* emb   = (const float*)d_in[2];    // [50000, 64]
    float* out = (float*)d_out;                    // [4096*50000] probs + [1] loss

    convert_kernel<<<(N_ROWS * DIM / 4 + VOCAB * DIM / 4 + 255) / 256, 256>>>(inp, emb);
    persistent_kernel<<<GRID_P, 256>>>(out);
    loss_kernel<<<N_ROWS / 256, 256>>>(label, inp, emb, out, (long long)out_size - 1);
}

// round 6
// speedup vs baseline: 2.5787x; 2.5787x over previous
#include <cuda_runtime.h>
#include <cuda_fp16.h>
#include <cstdint>

#define N_ROWS 4096
#define VOCAB  50000
#define DIM    64

#define BM 128
#define BN 128
#define TPB   391                 // column tiles per row-block
#define MB    32                  // row blocks
#define TOTAL (TPB * MB)          // 12512
#define GRID_P 296                // 2 CTAs/SM x 148 SMs, all resident

#define ROWB 144                  // bytes per smem tile row (72 halves, conflict-free)
#define A_SM_BYTES (BM * ROWB)    // 18432
#define SMEM_TOTAL (3 * A_SM_BYTES)   // A + B double buffer = 55296

// scratch (no allocs allowed -> device globals)
__device__ float  g_sums[N_ROWS];
__device__ float  g_loss;
__device__ int    g_loss_cnt;
__device__ __half g_A16[N_ROWS * DIM];
__device__ __half g_B16[VOCAB * DIM];

__device__ __forceinline__ uint32_t smem_u32(const void* p) {
    uint32_t a;
    asm("{ .reg .u64 t; cvta.to.shared.u64 t, %1; cvt.u32.u64 %0, t; }" : "=r"(a) : "l"(p));
    return a;
}
#define CP_ASYNC16(dst, src, sz) \
    asm volatile("cp.async.cg.shared.global [%0], [%1], 16, %2;" :: "r"(dst), "l"(src), "r"(sz))
#define CP_COMMIT()  asm volatile("cp.async.commit_group;" ::: "memory")
#define CP_WAIT0()   asm volatile("cp.async.wait_group 0;" ::: "memory")
#define LDMATRIX_X4(r0, r1, r2, r3, addr) \
    asm volatile("ldmatrix.sync.aligned.m8n8.x4.shared.b16 {%0,%1,%2,%3}, [%4];" \
                 : "=r"(r0), "=r"(r1), "=r"(r2), "=r"(r3) : "r"(addr))

// init + fp32 -> fp16 convert (fp16 keeps tf32's 10 mantissa bits)
__global__ void convert_kernel(const float* __restrict__ A, const float* __restrict__ B) {
    int i = blockIdx.x * blockDim.x + threadIdx.x;               // float4 index
    if (i < N_ROWS) g_sums[i] = 0.f;
    if (i == 0) { g_loss = 0.f; g_loss_cnt = 0; }
    const int nA4 = N_ROWS * DIM / 4;
    const int nB4 = VOCAB * DIM / 4;
    if (i < nA4) {
        float4 v = ((const float4*)A)[i];
        __half2* d = (__half2*)g_A16;
        d[i * 2 + 0] = __floats2half2_rn(v.x, v.y);
        d[i * 2 + 1] = __floats2half2_rn(v.z, v.w);
    }
    int j = i - nA4;
    if (j >= 0 && j < nB4) {
        float4 v = ((const float4*)B)[j];
        __half2* d = (__half2*)g_B16;
        d[j * 2 + 0] = __floats2half2_rn(v.x, v.y);
        d[j * 2 + 1] = __floats2half2_rn(v.z, v.w);
    }
}

// Persistent strip kernel. Each CTA owns 42-43 CONSECUTIVE tiles (A reused per
// row-block). B tiles double-buffered via cp.async, prefetched under MMA+epilogue.
// PASS 0: logits -> exp -> row-sum register accumulation -> atomic flush per m.
// PASS 1: logits -> exp * (1/g_sums[row]) -> streaming f32 prob stores.
template <int PASS>
__global__ void __launch_bounds__(256, 2)
gemm_softmax_kernel(float* __restrict__ out)        // [N_ROWS, VOCAB]
{
    extern __shared__ char smem[];
    __half* As = (__half*)smem;
    const uint32_t sA = smem_u32(smem);
    const uint32_t sB0 = sA + A_SM_BYTES;

    const int tid  = threadIdx.x;
    const int lane = tid & 31;
    const int wid  = tid >> 5;
    const int wm = wid >> 2, wn = wid & 3;
    const int mBase = wm * 64, nBase = wn * 32;
    const int lr = lane >> 2, lc = lane & 3;

    // ldmatrix per-lane base addresses (kk=0, mf/p=0)
    const uint32_t aAddr0 = sA +
        (uint32_t)(mBase + ((lane >> 3) & 1) * 8 + (lane & 7)) * ROWB + (lane >> 4) * 16;
    const uint32_t bOff0 =
        (uint32_t)(nBase + (lane >> 4) * 8 + (lane & 7)) * ROWB + ((lane >> 3) & 1) * 16;

    // balanced contiguous strips
    const int base = TOTAL / GRID_P, rem = TOTAL % GRID_P;
    const int b = blockIdx.x;
    const int gBeg = b * base + (b < rem ? b : rem);
    const int gEnd = gBeg + base + (b < rem ? 1 : 0);

    // prologue: prefetch first B tile into buffer 0
    {
        const int v0 = (gBeg % TPB) * BN;
        #pragma unroll
        for (int t = 0; t < 4; t++) {
            int i = tid + t * 256;                 // 16B chunk id, 0..1023
            int row = i >> 3, c8 = i & 7;
            uint32_t dst = sB0 + row * ROWB + c8 * 16;
            const __half* src = g_B16 + (size_t)(v0 + row) * DIM + c8 * 8;
            CP_ASYNC16(dst, src, (v0 + row < VOCAB) ? 16 : 0);
        }
        CP_COMMIT();
    }

    int curM = -1;
    int buf = 0;
    float racc[8];                                 // pass0 row-sum accumulators
    float rinv[8];                                 // pass1 reciprocal sums
    #pragma unroll
    for (int k = 0; k < 8; k++) { racc[k] = 0.f; rinv[k] = 0.f; }

    for (int g = gBeg; g < gEnd; g++) {
        const int m = g / TPB;
        const int v0 = (g % TPB) * BN;
        const int m0 = m * BM;

        if (m != curM) {                           // <=2 times per strip
            __syncthreads();                       // everyone done reading old As
            if (PASS == 0 && curM >= 0) {          // flush row sums of previous block
                #pragma unroll
                for (int k = 0; k < 8; k++) {
                    float s = racc[k];
                    s += __shfl_xor_sync(0xffffffffu, s, 1);
                    s += __shfl_xor_sync(0xffffffffu, s, 2);
                    if (lc == 0)
                        atomicAdd(&g_sums[curM * BM + mBase + (k >> 1) * 16 + (k & 1) * 8 + lr], s);
                    racc[k] = 0.f;
                }
            }
            const uint4* Ag = (const uint4*)(g_A16 + (size_t)m0 * DIM);
            #pragma unroll
            for (int t = 0; t < 4; t++) {
                int i = tid + t * 256;
                int row = i >> 3, c8 = i & 7;
                *(uint4*)((char*)As + row * ROWB + c8 * 16) = Ag[i];
            }
            if (PASS == 1) {
                #pragma unroll
                for (int k = 0; k < 8; k++)
                    rinv[k] = 1.0f / __ldcg(&g_sums[m0 + mBase + (k >> 1) * 16 + (k & 1) * 8 + lr]);
            }
            curM = m;
        }

        CP_WAIT0();                                // current B buffer landed
        __syncthreads();                           // visible CTA-wide; prev reads done

        // prefetch next B tile into the other buffer (overlaps MMA + epilogue)
        if (g + 1 < gEnd) {
            const int vn = ((g + 1) % TPB) * BN;
            const uint32_t sBn = sB0 + (buf ^ 1) * A_SM_BYTES;
            #pragma unroll
            for (int t = 0; t < 4; t++) {
                int i = tid + t * 256;
                int row = i >> 3, c8 = i & 7;
                uint32_t dst = sBn + row * ROWB + c8 * 16;
                const __half* src = g_B16 + (size_t)(vn + row) * DIM + c8 * 8;
                CP_ASYNC16(dst, src, (vn + row < VOCAB) ? 16 : 0);
            }
            CP_COMMIT();
        }

        // ---- MMA: K=64 = 4 k-steps of m16n8k16 (fragments via ldmatrix.x4) ----
        const uint32_t bAddr0 = sB0 + buf * A_SM_BYTES + bOff0;
        float c[4][4][4];
        #pragma unroll
        for (int a = 0; a < 4; a++)
            #pragma unroll
            for (int bb = 0; bb < 4; bb++)
                #pragma unroll
                for (int d = 0; d < 4; d++) c[a][bb][d] = 0.f;

        #pragma unroll
        for (int kk = 0; kk < 4; kk++) {
            unsigned af[4][4], bf[4][2];
            #pragma unroll
            for (int mf = 0; mf < 4; mf++)
                LDMATRIX_X4(af[mf][0], af[mf][1], af[mf][2], af[mf][3],
                            aAddr0 + mf * (16 * ROWB) + kk * 32);
            #pragma unroll
            for (int p = 0; p < 2; p++)
                LDMATRIX_X4(bf[2 * p][0], bf[2 * p][1], bf[2 * p + 1][0], bf[2 * p + 1][1],
                            bAddr0 + p * (16 * ROWB) + kk * 32);
            #pragma unroll
            for (int mf = 0; mf < 4; mf++)
                #pragma unroll
                for (int nf = 0; nf < 4; nf++) {
                    asm volatile(
                        "mma.sync.aligned.m16n8k16.row.col.f32.f16.f16.f32 "
                        "{%0,%1,%2,%3}, {%4,%5,%6,%7}, {%8,%9}, {%0,%1,%2,%3};"
                        : "+f"(c[mf][nf][0]), "+f"(c[mf][nf][1]),
                          "+f"(c[mf][nf][2]), "+f"(c[mf][nf][3])
                        : "r"(af[mf][0]), "r"(af[mf][1]), "r"(af[mf][2]), "r"(af[mf][3]),
                          "r"(bf[nf][0]), "r"(bf[nf][1]));
                }
        }

        // ---- epilogue ----
        const bool full = (v0 + BN <= VOCAB);
        if (PASS == 0) {
            #pragma unroll
            for (int mf = 0; mf < 4; mf++) {
                #pragma unroll
                for (int h = 0; h < 2; h++) {
                    float s = 0.f;
                    #pragma unroll
                    for (int nf = 0; nf < 4; nf++) {
                        float e0 = __expf(c[mf][nf][h * 2 + 0]);
                        float e1 = __expf(c[mf][nf][h * 2 + 1]);
                        if (full) { s += e0 + e1; }
                        else {
                            int col = v0 + nBase + nf * 8 + lc * 2;
                            s += (col     < VOCAB) ? e0 : 0.f;
                            s += (col + 1 < VOCAB) ? e1 : 0.f;
                        }
                    }
                    racc[mf * 2 + h] += s;
                }
            }
        } else {
            #pragma unroll
            for (int mf = 0; mf < 4; mf++) {
                #pragma unroll
                for (int h = 0; h < 2; h++) {
                    const float r = rinv[mf * 2 + h];
                    const int rl = mBase + mf * 16 + h * 8 + lr;
                    float* op = out + (size_t)(m0 + rl) * VOCAB;
                    #pragma unroll
                    for (int nf = 0; nf < 4; nf++) {
                        int col = v0 + nBase + nf * 8 + lc * 2;
                        if (full || col < VOCAB) {   // VOCAB even -> pair never straddles
                            float2 p;
                            p.x = __expf(c[mf][nf][h * 2 + 0]) * r;
                            p.y = __expf(c[mf][nf][h * 2 + 1]) * r;
                            __stcs((float2*)(op + col), p);
                        }
                    }
                }
            }
        }
        buf ^= 1;
    }

    if (PASS == 0 && curM >= 0) {                  // final flush
        #pragma unroll
        for (int k = 0; k < 8; k++) {
            float s = racc[k];
            s += __shfl_xor_sync(0xffffffffu, s, 1);
            s += __shfl_xor_sync(0xffffffffu, s, 2);
            if (lc == 0)
                atomicAdd(&g_sums[curM * BM + mBase + (k >> 1) * 16 + (k & 1) * 8 + lr], s);
        }
    }
}

// loss = mean_n( log(sum_n) - logit_label_n ); clip never binds (min prob ~2e-6 >> 1e-7)
// last finishing block writes the final scalar (finalize fused via counter).
__global__ void loss_kernel(const int* __restrict__ label_words,
                            const float* __restrict__ inp,
                            const float* __restrict__ emb,
                            float* __restrict__ out, long long idx) {
    int n = blockIdx.x * blockDim.x + threadIdx.x;

    // dtype sniff: int64 labels (< 2^31) have all odd 32-bit words == 0
    bool is64 = true;
    #pragma unroll
    for (int i = 0; i < 64; i++) is64 &= (label_words[2 * i + 1] == 0);

    float v = 0.f;
    if (n < N_ROWS) {
        int lab = is64 ? label_words[2 * n] : label_words[n];
        const float4* a = (const float4*)(inp + (size_t)n * DIM);
        const float4* b = (const float4*)(emb + (size_t)lab * DIM);
        float dot = 0.f;
        #pragma unroll
        for (int i = 0; i < DIM / 4; i++) {
            float4 x = a[i], y = b[i];
            dot += x.x * y.x + x.y * y.y + x.z * y.z + x.w * y.w;
        }
        v = logf(g_sums[n]) - dot;
    }
    __shared__ float red[256];
    red[threadIdx.x] = v;
    __syncthreads();
    for (int s = 128; s > 0; s >>= 1) {
        if (threadIdx.x < s) red[threadIdx.x] += red[threadIdx.x + s];
        __syncthreads();
    }
    if (threadIdx.x == 0) {
        atomicAdd(&g_loss, red[0]);
        __threadfence();
        int c = atomicAdd(&g_loss_cnt, 1);
        if (c == (int)gridDim.x - 1) {
            float total = atomicAdd(&g_loss, 0.f);   // ordered read of final sum
            out[idx] = total * (1.0f / (float)N_ROWS);
        }
    }
}

extern "C" void kernel_launch(void* const* d_in, const int* in_sizes, int n_in,
                              void* d_out, int out_size) {
    const int*   label = (const int*)d_in[0];      // int32 or int64 (sniffed in-kernel)
    const float* inp   = (const float*)d_in[1];    // [4096, 64]
    const float* emb   = (const float*)d_in[2];    // [50000, 64]
    float* out = (float*)d_out;                    // [4096*50000] probs + [1] loss

    static int attr_done = 0;
    if (!attr_done) {
        cudaFuncSetAttribute(gemm_softmax_kernel<0>,
                             cudaFuncAttributeMaxDynamicSharedMemorySize, SMEM_TOTAL);
        cudaFuncSetAttribute(gemm_softmax_kernel<1>,
                             cudaFuncAttributeMaxDynamicSharedMemorySize, SMEM_TOTAL);
        attr_done = 1;
    }

    convert_kernel<<<(N_ROWS * DIM / 4 + VOCAB * DIM / 4 + 255) / 256, 256>>>(inp, emb);
    gemm_softmax_kernel<0><<<GRID_P, 256, SMEM_TOTAL>>>(out);
    loss_kernel<<<N_ROWS / 256, 256>>>(label, inp, emb, out, (long long)out_size - 1);
    gemm_softmax_kernel<1><<<GRID_P, 256, SMEM_TOTAL>>>(out);
}

// round 7
// speedup vs baseline: 2.8591x; 1.1087x over previous
#include <cuda_runtime.h>
#include <cuda_fp16.h>
#include <cstdint>

#define N_ROWS 4096
#define VOCAB  50000
#define DIM    64

#define BM 128
#define BN 128
#define TPB   391                 // column tiles per row-block
#define MB    32                  // row blocks
#define TOTAL (TPB * MB)          // 12512
#define GRID_P 296                // 2 CTAs/SM x 148 SMs, all resident
#define LOSS_BLOCKS 16

#define ROWB 144                  // bytes per smem tile row (72 halves, conflict-free)
#define A_SM_BYTES (BM * ROWB)    // 18432
#define SMEM_TOTAL (3 * A_SM_BYTES)   // A + B double buffer = 55296

#define LOG2E 1.4426950408889634f

// scratch (no allocs allowed -> device globals)
__device__ float  g_sums[N_ROWS];
__device__ float  g_loss;
__device__ int    g_loss_cnt;
__device__ __half g_A16[N_ROWS * DIM];   // pre-scaled by log2e
__device__ __half g_B16[VOCAB * DIM];

__device__ __forceinline__ uint32_t smem_u32(const void* p) {
    uint32_t a;
    asm("{ .reg .u64 t; cvta.to.shared.u64 t, %1; cvt.u32.u64 %0, t; }" : "=r"(a) : "l"(p));
    return a;
}
__device__ __forceinline__ float ex2f(float x) {      // exp(logit): logits are log2-domain
    float y;
    asm("ex2.approx.f32 %0, %1;" : "=f"(y) : "f"(x));
    return y;
}
#define CP_ASYNC16(dst, src, sz) \
    asm volatile("cp.async.cg.shared.global [%0], [%1], 16, %2;" :: "r"(dst), "l"(src), "r"(sz))
#define CP_COMMIT()  asm volatile("cp.async.commit_group;" ::: "memory")
#define CP_WAIT0()   asm volatile("cp.async.wait_group 0;" ::: "memory")
#define LDMATRIX_X4(r0, r1, r2, r3, addr) \
    asm volatile("ldmatrix.sync.aligned.m8n8.x4.shared.b16 {%0,%1,%2,%3}, [%4];" \
                 : "=r"(r0), "=r"(r1), "=r"(r2), "=r"(r3) : "r"(addr))

// init + fp32 -> fp16 convert. A is pre-scaled by log2e so exp(logit) == ex2(gemm_out).
__global__ void convert_kernel(const float* __restrict__ A, const float* __restrict__ B) {
    int i = blockIdx.x * blockDim.x + threadIdx.x;               // float4 index
    if (i < N_ROWS) g_sums[i] = 0.f;
    if (i == 0) { g_loss = 0.f; g_loss_cnt = 0; }
    const int nA4 = N_ROWS * DIM / 4;
    const int nB4 = VOCAB * DIM / 4;
    if (i < nA4) {
        float4 v = ((const float4*)A)[i];
        __half2* d = (__half2*)g_A16;
        d[i * 2 + 0] = __floats2half2_rn(v.x * LOG2E, v.y * LOG2E);
        d[i * 2 + 1] = __floats2half2_rn(v.z * LOG2E, v.w * LOG2E);
    }
    int j = i - nA4;
    if (j >= 0 && j < nB4) {
        float4 v = ((const float4*)B)[j];
        __half2* d = (__half2*)g_B16;
        d[j * 2 + 0] = __floats2half2_rn(v.x, v.y);
        d[j * 2 + 1] = __floats2half2_rn(v.z, v.w);
    }
}

// Persistent strip kernel; contiguous tiles per CTA; cp.async double-buffered B.
// PASS 0: logits -> ex2 (f16x2 pairs) -> row-sum register accum -> atomic flush per m.
// PASS 1: loss (blocks 0..15) then logits -> ex2 * (1/g_sums[row]) -> streaming stores.
template <int PASS>
__global__ void __launch_bounds__(256, 2)
gemm_softmax_kernel(float* __restrict__ out,
                    const int* __restrict__ label_words,
                    const float* __restrict__ inp,
                    const float* __restrict__ emb,
                    long long lossIdx)
{
    extern __shared__ char smem[];
    __half* As = (__half*)smem;
    const uint32_t sA = smem_u32(smem);
    const uint32_t sB0 = sA + A_SM_BYTES;

    const int tid  = threadIdx.x;
    const int lane = tid & 31;
    const int wid  = tid >> 5;
    const int wm = wid >> 2, wn = wid & 3;
    const int mBase = wm * 64, nBase = wn * 32;
    const int lr = lane >> 2, lc = lane & 3;

    // ldmatrix per-lane base addresses (kk=0, mf/p=0)
    const uint32_t aAddr0 = sA +
        (uint32_t)(mBase + ((lane >> 3) & 1) * 8 + (lane & 7)) * ROWB + (lane >> 4) * 16;
    const uint32_t bOff0 =
        (uint32_t)(nBase + (lane >> 4) * 8 + (lane & 7)) * ROWB + ((lane >> 3) & 1) * 16;

    // balanced contiguous strips; remainder tiles go to HIGH block ids so the
    // loss blocks (0..15) get the short strips
    const int base = TOTAL / GRID_P, rem = TOTAL % GRID_P;
    const int b = blockIdx.x;
    const int cut = GRID_P - rem;
    const int gBeg = b * base + (b > cut ? b - cut : 0);
    const int gEnd = gBeg + base + (b >= cut ? 1 : 0);

    // prologue: prefetch first B tile into buffer 0 (async; overlaps loss below)
    {
        const int v0 = (gBeg % TPB) * BN;
        #pragma unroll
        for (int t = 0; t < 4; t++) {
            int i = tid + t * 256;                 // 16B chunk id, 0..1023
            int row = i >> 3, c8 = i & 7;
            uint32_t dst = sB0 + row * ROWB + c8 * 16;
            const __half* src = g_B16 + (size_t)(v0 + row) * DIM + c8 * 8;
            CP_ASYNC16(dst, src, (v0 + row < VOCAB) ? 16 : 0);
        }
        CP_COMMIT();
    }

    // ---- fused loss (PASS 1, blocks 0..15): sums are final before this kernel ----
    if (PASS == 1 && b < LOSS_BLOCKS) {
        int n = b * 256 + tid;
        bool is64 = true;                          // int64 labels: odd words all zero
        #pragma unroll
        for (int i = 0; i < 64; i++) is64 &= (label_words[2 * i + 1] == 0);
        int lab = is64 ? label_words[2 * n] : label_words[n];
        const float4* a4 = (const float4*)(inp + (size_t)n * DIM);
        const float4* b4 = (const float4*)(emb + (size_t)lab * DIM);
        float dot = 0.f;
        #pragma unroll
        for (int i = 0; i < DIM / 4; i++) {
            float4 x = a4[i], y = b4[i];
            dot += x.x * y.x + x.y * y.y + x.z * y.z + x.w * y.w;
        }
        float v = logf(g_sums[n]) - dot;
        float* red = (float*)smem;                 // A region; A not loaded yet
        red[tid] = v;
        __syncthreads();
        for (int s = 128; s > 0; s >>= 1) {
            if (tid < s) red[tid] += red[tid + s];
            __syncthreads();
        }
        if (tid == 0) {
            atomicAdd(&g_loss, red[0]);
            __threadfence();
            int c = atomicAdd(&g_loss_cnt, 1);
            if (c == LOSS_BLOCKS - 1)
                out[lossIdx] = atomicAdd(&g_loss, 0.f) * (1.0f / (float)N_ROWS);
        }
    }

    int curM = -1;
    int buf = 0;
    float racc[8];                                 // pass0 row-sum accumulators
    float rinv[8];                                 // pass1 reciprocal sums
    #pragma unroll
    for (int k = 0; k < 8; k++) { racc[k] = 0.f; rinv[k] = 0.f; }

    for (int g = gBeg; g < gEnd; g++) {
        const int m = g / TPB;
        const int v0 = (g % TPB) * BN;
        const int m0 = m * BM;

        if (m != curM) {                           // <=2 times per strip
            __syncthreads();                       // everyone done with old As
            if (PASS == 0 && curM >= 0) {          // flush row sums of previous block
                #pragma unroll
                for (int k = 0; k < 8; k++) {
                    float s = racc[k];
                    s += __shfl_xor_sync(0xffffffffu, s, 1);
                    s += __shfl_xor_sync(0xffffffffu, s, 2);
                    if (lc == 0)
                        atomicAdd(&g_sums[curM * BM + mBase + (k >> 1) * 16 + (k & 1) * 8 + lr], s);
                    racc[k] = 0.f;
                }
            }
            const uint4* Ag = (const uint4*)(g_A16 + (size_t)m0 * DIM);
            #pragma unroll
            for (int t = 0; t < 4; t++) {
                int i = tid + t * 256;
                int row = i >> 3, c8 = i & 7;
                *(uint4*)((char*)As + row * ROWB + c8 * 16) = Ag[i];
            }
            if (PASS == 1) {
                #pragma unroll
                for (int k = 0; k < 8; k++)
                    rinv[k] = 1.0f / __ldcg(&g_sums[m0 + mBase + (k >> 1) * 16 + (k & 1) * 8 + lr]);
            }
            curM = m;
        }

        CP_WAIT0();                                // current B buffer landed
        __syncthreads();

        // prefetch next B tile into the other buffer (overlaps MMA + epilogue)
        if (g + 1 < gEnd) {
            const int vn = ((g + 1) % TPB) * BN;
            const uint32_t sBn = sB0 + (buf ^ 1) * A_SM_BYTES;
            #pragma unroll
            for (int t = 0; t < 4; t++) {
                int i = tid + t * 256;
                int row = i >> 3, c8 = i & 7;
                uint32_t dst = sBn + row * ROWB + c8 * 16;
                const __half* src = g_B16 + (size_t)(vn + row) * DIM + c8 * 8;
                CP_ASYNC16(dst, src, (vn + row < VOCAB) ? 16 : 0);
            }
            CP_COMMIT();
        }

        // ---- MMA: K=64 = 4 k-steps of m16n8k16 (fragments via ldmatrix.x4) ----
        const uint32_t bAddr0 = sB0 + buf * A_SM_BYTES + bOff0;
        float c[4][4][4];
        #pragma unroll
        for (int a = 0; a < 4; a++)
            #pragma unroll
            for (int bb = 0; bb < 4; bb++)
                #pragma unroll
                for (int d = 0; d < 4; d++) c[a][bb][d] = 0.f;

        #pragma unroll
        for (int kk = 0; kk < 4; kk++) {
            unsigned af[4][4], bf[4][2];
            #pragma unroll
            for (int mf = 0; mf < 4; mf++)
                LDMATRIX_X4(af[mf][0], af[mf][1], af[mf][2], af[mf][3],
                            aAddr0 + mf * (16 * ROWB) + kk * 32);
            #pragma unroll
            for (int p = 0; p < 2; p++)
                LDMATRIX_X4(bf[2 * p][0], bf[2 * p][1], bf[2 * p + 1][0], bf[2 * p + 1][1],
                            bAddr0 + p * (16 * ROWB) + kk * 32);
            #pragma unroll
            for (int mf = 0; mf < 4; mf++)
                #pragma unroll
                for (int nf = 0; nf < 4; nf++) {
                    asm volatile(
                        "mma.sync.aligned.m16n8k16.row.col.f32.f16.f16.f32 "
                        "{%0,%1,%2,%3}, {%4,%5,%6,%7}, {%8,%9}, {%0,%1,%2,%3};"
                        : "+f"(c[mf][nf][0]), "+f"(c[mf][nf][1]),
                          "+f"(c[mf][nf][2]), "+f"(c[mf][nf][3])
                        : "r"(af[mf][0]), "r"(af[mf][1]), "r"(af[mf][2]), "r"(af[mf][3]),
                          "r"(bf[nf][0]), "r"(bf[nf][1]));
                }
        }

        // ---- epilogue (logits are log2-domain: exp == ex2) ----
        const bool full = (v0 + BN <= VOCAB);
        if (PASS == 0) {
            if (full) {
                #pragma unroll
                for (int mf = 0; mf < 4; mf++) {
                    #pragma unroll
                    for (int h = 0; h < 2; h++) {
                        __half2 hs = __floats2half2_rn(0.f, 0.f);
                        #pragma unroll
                        for (int nf = 0; nf < 4; nf++) {
                            __half2 p = __floats2half2_rn(c[mf][nf][h * 2 + 0],
                                                          c[mf][nf][h * 2 + 1]);
                            hs = __hadd2(hs, h2exp2(p));   // ex2.approx.f16x2
                        }
                        float2 f = __half22float2(hs);
                        racc[mf * 2 + h] += f.x + f.y;
                    }
                }
            } else {                               // 32 of 12512 tiles: masked scalar path
                #pragma unroll
                for (int mf = 0; mf < 4; mf++) {
                    #pragma unroll
                    for (int h = 0; h < 2; h++) {
                        float s = 0.f;
                        #pragma unroll
                        for (int nf = 0; nf < 4; nf++) {
                            int col = v0 + nBase + nf * 8 + lc * 2;
                            float e0 = ex2f(c[mf][nf][h * 2 + 0]);
                            float e1 = ex2f(c[mf][nf][h * 2 + 1]);
                            s += (col     < VOCAB) ? e0 : 0.f;
                            s += (col + 1 < VOCAB) ? e1 : 0.f;
                        }
                        racc[mf * 2 + h] += s;
                    }
                }
            }
        } else {
            #pragma unroll
            for (int mf = 0; mf < 4; mf++) {
                #pragma unroll
                for (int h = 0; h < 2; h++) {
                    const float r = rinv[mf * 2 + h];
                    const int rl = mBase + mf * 16 + h * 8 + lr;
                    float* op = out + (size_t)(m0 + rl) * VOCAB;
                    #pragma unroll
                    for (int nf = 0; nf < 4; nf++) {
                        int col = v0 + nBase + nf * 8 + lc * 2;
                        if (full || col < VOCAB) {   // VOCAB even -> pair never straddles
                            float2 p;
                            p.x = ex2f(c[mf][nf][h * 2 + 0]) * r;
                            p.y = ex2f(c[mf][nf][h * 2 + 1]) * r;
                            __stcs((float2*)(op + col), p);
                        }
                    }
                }
            }
        }
        buf ^= 1;
    }

    if (PASS == 0 && curM >= 0) {                  // final flush
        #pragma unroll
        for (int k = 0; k < 8; k++) {
            float s = racc[k];
            s += __shfl_xor_sync(0xffffffffu, s, 1);
            s += __shfl_xor_sync(0xffffffffu, s, 2);
            if (lc == 0)
                atomicAdd(&g_sums[curM * BM + mBase + (k >> 1) * 16 + (k & 1) * 8 + lr], s);
        }
    }
}

extern "C" void kernel_launch(void* const* d_in, const int* in_sizes, int n_in,
                              void* d_out, int out_size) {
    const int*   label = (const int*)d_in[0];      // int32 or int64 (sniffed in-kernel)
    const float* inp   = (const float*)d_in[1];    // [4096, 64]
    const float* emb   = (const float*)d_in[2];    // [50000, 64]
    float* out = (float*)d_out;                    // [4096*50000] probs + [1] loss

    static int attr_done = 0;
    if (!attr_done) {
        cudaFuncSetAttribute(gemm_softmax_kernel<0>,
                             cudaFuncAttributeMaxDynamicSharedMemorySize, SMEM_TOTAL);
        cudaFuncSetAttribute(gemm_softmax_kernel<1>,
                             cudaFuncAttributeMaxDynamicSharedMemorySize, SMEM_TOTAL);
        attr_done = 1;
    }
    long long lossIdx = (long long)out_size - 1;

    convert_kernel<<<(N_ROWS * DIM / 4 + VOCAB * DIM / 4 + 255) / 256, 256>>>(inp, emb);
    gemm_softmax_kernel<0><<<GRID_P, 256, SMEM_TOTAL>>>(out, label, inp, emb, lossIdx);
    gemm_softmax_kernel<1><<<GRID_P, 256, SMEM_TOTAL>>>(out, label, inp, emb, lossIdx);
}

// round 8
// speedup vs baseline: 3.0526x; 1.0677x over previous
#include <cuda_runtime.h>
#include <cuda_fp16.h>
#include <cstdint>

#define N_ROWS 4096
#define VOCAB  50000
#define DIM    64

#define BM 128
#define BN 128
#define TPB   391                 // column tiles per row-block
#define MB    32                  // row blocks
#define TOTAL (TPB * MB)          // 12512
#define GRID_P 296                // 2 CTAs/SM x 148 SMs, all resident
#define LOSS_BLOCKS 16

#define ROWB 144                  // bytes per smem tile row (72 halves, conflict-free)
#define A_SM_BYTES (BM * ROWB)    // 18432
#define SMEM_TOTAL (3 * A_SM_BYTES)   // A + B double buffer = 55296

#define LOG2E 1.4426950408889634f

// scratch (no allocs allowed -> device globals)
__device__ float  g_sums[N_ROWS];
__device__ float  g_loss;
__device__ int    g_loss_cnt;
__device__ __half g_A16[N_ROWS * DIM];   // pre-scaled by log2e
__device__ __half g_B16[VOCAB * DIM];

__device__ __forceinline__ uint32_t smem_u32(const void* p) {
    uint32_t a;
    asm("{ .reg .u64 t; cvta.to.shared.u64 t, %1; cvt.u32.u64 %0, t; }" : "=r"(a) : "l"(p));
    return a;
}
__device__ __forceinline__ float ex2f(float x) {      // exp(logit): logits are log2-domain
    float y;
    asm("ex2.approx.f32 %0, %1;" : "=f"(y) : "f"(x));
    return y;
}
// B-tile column permutation (within each 32-row group): smem MMA-space row
// q = nf*8 + lc*2 + j holds natural column n = (nf&2)*8 + lc*4 + (nf&1)*2 + j.
// After this, thread lc's fragments (nf pair) cover 4 CONSECUTIVE vocab columns
// -> pass-1 stores become full-sector STG.128.
__device__ __forceinline__ int permB(int r) {
    int q = r & 31;
    int nf = q >> 3, lc = (q >> 1) & 3, j = q & 1;
    return (r & ~31) | ((nf & 2) << 3) | (lc << 2) | ((nf & 1) << 1) | j;
}
#define CP_ASYNC16(dst, src, sz) \
    asm volatile("cp.async.cg.shared.global [%0], [%1], 16, %2;" :: "r"(dst), "l"(src), "r"(sz))
#define CP_COMMIT()  asm volatile("cp.async.commit_group;" ::: "memory")
#define CP_WAIT0()   asm volatile("cp.async.wait_group 0;" ::: "memory")
#define LDMATRIX_X4(r0, r1, r2, r3, addr) \
    asm volatile("ldmatrix.sync.aligned.m8n8.x4.shared.b16 {%0,%1,%2,%3}, [%4];" \
                 : "=r"(r0), "=r"(r1), "=r"(r2), "=r"(r3) : "r"(addr))

// init + fp32 -> fp16 convert. A is pre-scaled by log2e so exp(logit) == ex2(gemm_out).
__global__ void convert_kernel(const float* __restrict__ A, const float* __restrict__ B) {
    int i = blockIdx.x * blockDim.x + threadIdx.x;               // float4 index
    if (i < N_ROWS) g_sums[i] = 0.f;
    if (i == 0) { g_loss = 0.f; g_loss_cnt = 0; }
    const int nA4 = N_ROWS * DIM / 4;
    const int nB4 = VOCAB * DIM / 4;
    if (i < nA4) {
        float4 v = ((const float4*)A)[i];
        __half2* d = (__half2*)g_A16;
        d[i * 2 + 0] = __floats2half2_rn(v.x * LOG2E, v.y * LOG2E);
        d[i * 2 + 1] = __floats2half2_rn(v.z * LOG2E, v.w * LOG2E);
    }
    int j = i - nA4;
    if (j >= 0 && j < nB4) {
        float4 v = ((const float4*)B)[j];
        __half2* d = (__half2*)g_B16;
        d[j * 2 + 0] = __floats2half2_rn(v.x, v.y);
        d[j * 2 + 1] = __floats2half2_rn(v.z, v.w);
    }
}

// Persistent strip kernel; contiguous tiles per CTA; cp.async double-buffered B.
// PASS 0: logits -> ex2 (f16x2 pairs) -> row-sum register accum -> atomic flush per m.
// PASS 1: loss (blocks 0..15) then logits -> ex2 * (1/sum) -> STG.128 streaming stores.
template <int PASS>
__global__ void __launch_bounds__(256, 2)
gemm_softmax_kernel(float* __restrict__ out,
                    const int* __restrict__ label_words,
                    const float* __restrict__ inp,
                    const float* __restrict__ emb,
                    long long lossIdx)
{
    extern __shared__ char smem[];
    __half* As = (__half*)smem;
    const uint32_t sA = smem_u32(smem);
    const uint32_t sB0 = sA + A_SM_BYTES;

    const int tid  = threadIdx.x;
    const int lane = tid & 31;
    const int wid  = tid >> 5;
    const int wm = wid >> 2, wn = wid & 3;
    const int mBase = wm * 64, nBase = wn * 32;
    const int lr = lane >> 2, lc = lane & 3;

    // ldmatrix per-lane base addresses (kk=0, mf/p=0)
    const uint32_t aAddr0 = sA +
        (uint32_t)(mBase + ((lane >> 3) & 1) * 8 + (lane & 7)) * ROWB + (lane >> 4) * 16;
    const uint32_t bOff0 =
        (uint32_t)(nBase + (lane >> 4) * 8 + (lane & 7)) * ROWB + ((lane >> 3) & 1) * 16;

    // balanced contiguous strips; remainder tiles go to HIGH block ids so the
    // loss blocks (0..15) get the short strips
    const int base = TOTAL / GRID_P, rem = TOTAL % GRID_P;
    const int b = blockIdx.x;
    const int cut = GRID_P - rem;
    const int gBeg = b * base + (b > cut ? b - cut : 0);
    const int gEnd = gBeg + base + (b >= cut ? 1 : 0);

    // prologue: prefetch first B tile into buffer 0 (async; overlaps loss below)
    {
        const int v0 = (gBeg % TPB) * BN;
        #pragma unroll
        for (int t = 0; t < 4; t++) {
            int i = tid + t * 256;                 // 16B chunk id, 0..1023
            int row = i >> 3, c8 = i & 7;
            int v = v0 + permB(row);
            uint32_t dst = sB0 + row * ROWB + c8 * 16;
            const __half* src = g_B16 + (size_t)v * DIM + c8 * 8;
            CP_ASYNC16(dst, src, (v < VOCAB) ? 16 : 0);
        }
        CP_COMMIT();
    }

    // ---- fused loss (PASS 1, blocks 0..15): sums are final before this kernel ----
    if (PASS == 1 && b < LOSS_BLOCKS) {
        int n = b * 256 + tid;
        bool is64 = true;                          // int64 labels: odd words all zero
        #pragma unroll
        for (int i = 0; i < 64; i++) is64 &= (label_words[2 * i + 1] == 0);
        int lab = is64 ? label_words[2 * n] : label_words[n];
        const float4* a4 = (const float4*)(inp + (size_t)n * DIM);
        const float4* b4 = (const float4*)(emb + (size_t)lab * DIM);
        float dot = 0.f;
        #pragma unroll
        for (int i = 0; i < DIM / 4; i++) {
            float4 x = a4[i], y = b4[i];
            dot += x.x * y.x + x.y * y.y + x.z * y.z + x.w * y.w;
        }
        float v = logf(g_sums[n]) - dot;
        float* red = (float*)smem;                 // A region; A not loaded yet
        red[tid] = v;
        __syncthreads();
        for (int s = 128; s > 0; s >>= 1) {
            if (tid < s) red[tid] += red[tid + s];
            __syncthreads();
        }
        if (tid == 0) {
            atomicAdd(&g_loss, red[0]);
            __threadfence();
            int c = atomicAdd(&g_loss_cnt, 1);
            if (c == LOSS_BLOCKS - 1)
                out[lossIdx] = atomicAdd(&g_loss, 0.f) * (1.0f / (float)N_ROWS);
        }
    }

    int curM = -1;
    int buf = 0;
    float racc[8];                                 // pass0 row-sum accumulators
    float rinv[8];                                 // pass1 reciprocal sums
    #pragma unroll
    for (int k = 0; k < 8; k++) { racc[k] = 0.f; rinv[k] = 0.f; }

    for (int g = gBeg; g < gEnd; g++) {
        const int m = g / TPB;
        const int v0 = (g % TPB) * BN;
        const int m0 = m * BM;

        if (m != curM) {                           // <=2 times per strip
            __syncthreads();                       // everyone done with old As
            if (PASS == 0 && curM >= 0) {          // flush row sums of previous block
                #pragma unroll
                for (int k = 0; k < 8; k++) {
                    float s = racc[k];
                    s += __shfl_xor_sync(0xffffffffu, s, 1);
                    s += __shfl_xor_sync(0xffffffffu, s, 2);
                    if (lc == 0)
                        atomicAdd(&g_sums[curM * BM + mBase + (k >> 1) * 16 + (k & 1) * 8 + lr], s);
                    racc[k] = 0.f;
                }
            }
            const uint4* Ag = (const uint4*)(g_A16 + (size_t)m0 * DIM);
            #pragma unroll
            for (int t = 0; t < 4; t++) {
                int i = tid + t * 256;
                int row = i >> 3, c8 = i & 7;
                *(uint4*)((char*)As + row * ROWB + c8 * 16) = Ag[i];
            }
            if (PASS == 1) {
                #pragma unroll
                for (int k = 0; k < 8; k++)
                    rinv[k] = 1.0f / __ldcg(&g_sums[m0 + mBase + (k >> 1) * 16 + (k & 1) * 8 + lr]);
            }
            curM = m;
        }

        CP_WAIT0();                                // current B buffer landed
        __syncthreads();

        // prefetch next B tile into the other buffer (overlaps MMA + epilogue)
        if (g + 1 < gEnd) {
            const int vn = ((g + 1) % TPB) * BN;
            const uint32_t sBn = sB0 + (buf ^ 1) * A_SM_BYTES;
            #pragma unroll
            for (int t = 0; t < 4; t++) {
                int i = tid + t * 256;
                int row = i >> 3, c8 = i & 7;
                int v = vn + permB(row);
                uint32_t dst = sBn + row * ROWB + c8 * 16;
                const __half* src = g_B16 + (size_t)v * DIM + c8 * 8;
                CP_ASYNC16(dst, src, (v < VOCAB) ? 16 : 0);
            }
            CP_COMMIT();
        }

        // ---- MMA: K=64 = 4 k-steps of m16n8k16 (fragments via ldmatrix.x4) ----
        const uint32_t bAddr0 = sB0 + buf * A_SM_BYTES + bOff0;
        float c[4][4][4];
        #pragma unroll
        for (int a = 0; a < 4; a++)
            #pragma unroll
            for (int bb = 0; bb < 4; bb++)
                #pragma unroll
                for (int d = 0; d < 4; d++) c[a][bb][d] = 0.f;

        #pragma unroll
        for (int kk = 0; kk < 4; kk++) {
            unsigned af[4][4], bf[4][2];
            #pragma unroll
            for (int mf = 0; mf < 4; mf++)
                LDMATRIX_X4(af[mf][0], af[mf][1], af[mf][2], af[mf][3],
                            aAddr0 + mf * (16 * ROWB) + kk * 32);
            #pragma unroll
            for (int p = 0; p < 2; p++)
                LDMATRIX_X4(bf[2 * p][0], bf[2 * p][1], bf[2 * p + 1][0], bf[2 * p + 1][1],
                            bAddr0 + p * (16 * ROWB) + kk * 32);
            #pragma unroll
            for (int mf = 0; mf < 4; mf++)
                #pragma unroll
                for (int nf = 0; nf < 4; nf++) {
                    asm volatile(
                        "mma.sync.aligned.m16n8k16.row.col.f32.f16.f16.f32 "
                        "{%0,%1,%2,%3}, {%4,%5,%6,%7}, {%8,%9}, {%0,%1,%2,%3};"
                        : "+f"(c[mf][nf][0]), "+f"(c[mf][nf][1]),
                          "+f"(c[mf][nf][2]), "+f"(c[mf][nf][3])
                        : "r"(af[mf][0]), "r"(af[mf][1]), "r"(af[mf][2]), "r"(af[mf][3]),
                          "r"(bf[nf][0]), "r"(bf[nf][1]));
                }
        }

        // ---- epilogue (logits log2-domain; fragment (nf,j) -> natural col
        //      v0 + nBase + (nf>>1)*16 + lc*4 + (nf&1)*2 + j  under permB) ----
        const bool full = (v0 + BN <= VOCAB);
        if (PASS == 0) {
            if (full) {                            // sum is permutation-invariant
                #pragma unroll
                for (int mf = 0; mf < 4; mf++) {
                    #pragma unroll
                    for (int h = 0; h < 2; h++) {
                        __half2 hs = __floats2half2_rn(0.f, 0.f);
                        #pragma unroll
                        for (int nf = 0; nf < 4; nf++) {
                            __half2 p = __floats2half2_rn(c[mf][nf][h * 2 + 0],
                                                          c[mf][nf][h * 2 + 1]);
                            hs = __hadd2(hs, h2exp2(p));   // ex2.approx.f16x2
                        }
                        float2 f = __half22float2(hs);
                        racc[mf * 2 + h] += f.x + f.y;
                    }
                }
            } else {                               // 32 of 12512 tiles: masked scalar path
                #pragma unroll
                for (int mf = 0; mf < 4; mf++) {
                    #pragma unroll
                    for (int h = 0; h < 2; h++) {
                        float s = 0.f;
                        #pragma unroll
                        for (int nf = 0; nf < 4; nf++) {
                            int col = v0 + nBase + (nf >> 1) * 16 + lc * 4 + (nf & 1) * 2;
                            float e0 = ex2f(c[mf][nf][h * 2 + 0]);
                            float e1 = ex2f(c[mf][nf][h * 2 + 1]);
                            s += (col     < VOCAB) ? e0 : 0.f;
                            s += (col + 1 < VOCAB) ? e1 : 0.f;
                        }
                        racc[mf * 2 + h] += s;
                    }
                }
            }
        } else {
            #pragma unroll
            for (int mf = 0; mf < 4; mf++) {
                #pragma unroll
                for (int h = 0; h < 2; h++) {
                    const float r = rinv[mf * 2 + h];
                    const int rl = mBase + mf * 16 + h * 8 + lr;
                    float* op = out + (size_t)(m0 + rl) * VOCAB;
                    #pragma unroll
                    for (int gg = 0; gg < 2; gg++) {
                        int col = v0 + nBase + gg * 16 + lc * 4;
                        if (full || col < VOCAB) {   // 50000 % 4 == 0 -> no straddle
                            float4 p;
                            p.x = ex2f(c[mf][2 * gg + 0][h * 2 + 0]) * r;
                            p.y = ex2f(c[mf][2 * gg + 0][h * 2 + 1]) * r;
                            p.z = ex2f(c[mf][2 * gg + 1][h * 2 + 0]) * r;
                            p.w = ex2f(c[mf][2 * gg + 1][h * 2 + 1]) * r;
                            __stcs((float4*)(op + col), p);
                        }
                    }
                }
            }
        }
        buf ^= 1;
    }

    if (PASS == 0 && curM >= 0) {                  // final flush
        #pragma unroll
        for (int k = 0; k < 8; k++) {
            float s = racc[k];
            s += __shfl_xor_sync(0xffffffffu, s, 1);
            s += __shfl_xor_sync(0xffffffffu, s, 2);
            if (lc == 0)
                atomicAdd(&g_sums[curM * BM + mBase + (k >> 1) * 16 + (k & 1) * 8 + lr], s);
        }
    }
}

extern "C" void kernel_launch(void* const* d_in, const int* in_sizes, int n_in,
                              void* d_out, int out_size) {
    const int*   label = (const int*)d_in[0];      // int32 or int64 (sniffed in-kernel)
    const float* inp   = (const float*)d_in[1];    // [4096, 64]
    const float* emb   = (const float*)d_in[2];    // [50000, 64]
    float* out = (float*)d_out;                    // [4096*50000] probs + [1] loss

    static int attr_done = 0;
    if (!attr_done) {
        cudaFuncSetAttribute(gemm_softmax_kernel<0>,
                             cudaFuncAttributeMaxDynamicSharedMemorySize, SMEM_TOTAL);
        cudaFuncSetAttribute(gemm_softmax_kernel<1>,
                             cudaFuncAttributeMaxDynamicSharedMemorySize, SMEM_TOTAL);
        attr_done = 1;
    }
    long long lossIdx = (long long)out_size - 1;

    convert_kernel<<<(N_ROWS * DIM / 4 + VOCAB * DIM / 4 + 255) / 256, 256>>>(inp, emb);
    gemm_softmax_kernel<0><<<GRID_P, 256, SMEM_TOTAL>>>(out, label, inp, emb, lossIdx);
    gemm_softmax_kernel<1><<<GRID_P, 256, SMEM_TOTAL>>>(out, label, inp, emb, lossIdx);
}